// round 1
// baseline (speedup 1.0000x reference)
#include <cuda_runtime.h>
#include <math.h>

#define N_NODES 100000
#define N_EDGES 1600000
#define IN_DIM  512
#define HID     64
#define OUTD    32

// ---------------- scratch (static device globals; no allocation) ----------------
__device__ int   g_deg[N_NODES];
__device__ float g_dinv[N_NODES];
__device__ int   g_off[N_NODES + 1];
__device__ int   g_cur[N_NODES];
__device__ int   g_srcs[N_EDGES];
__device__ float g_h1[(size_t)N_NODES * HID];   // 25.6 MB
__device__ float g_h2[(size_t)N_NODES * OUTD];  // 12.8 MB
__device__ int   g_bsum[256];
__device__ int   g_is64;

// ---------------- edge-index dtype detection (int64 vs int32) ----------------
// If the buffer is int32, interpreting pairs as int64 yields values >= 2^32
// with overwhelming probability over 2048 samples (values are U[0,100000)).
__global__ void k_detect(const long long* __restrict__ ei) {
    __shared__ int ok;
    if (threadIdx.x == 0) ok = 1;
    __syncthreads();
    for (int j = threadIdx.x; j < 2048; j += blockDim.x) {
        long long v = ei[j];
        if (v < 0 || v >= N_NODES) atomicExch(&ok, 0);
    }
    __syncthreads();
    if (threadIdx.x == 0) g_is64 = ok;
}

__device__ __forceinline__ int load_edge(const void* ei, int part, int e) {
    if (g_is64) return (int)((const long long*)ei)[(size_t)part * N_EDGES + e];
    return ((const int*)ei)[(size_t)part * N_EDGES + e];
}

// ---------------- degree / normalization ----------------
__global__ void k_init() {
    int v = blockIdx.x * blockDim.x + threadIdx.x;
    if (v < N_NODES) g_deg[v] = 1;  // self-loop
}

__global__ void k_hist(const void* __restrict__ ei) {
    int e = blockIdx.x * blockDim.x + threadIdx.x;
    if (e < N_EDGES) atomicAdd(&g_deg[load_edge(ei, 1, e)], 1);
}

__global__ void k_dinv() {
    int v = blockIdx.x * blockDim.x + threadIdx.x;
    if (v < N_NODES) g_dinv[v] = rsqrtf((float)g_deg[v]);
}

// ---------------- exclusive scan of (deg-1) to build CSR offsets ----------------
__global__ void k_scan1() {
    __shared__ int s[512];
    int t = threadIdx.x;
    int v = blockIdx.x * 512 + t;
    int c = (v < N_NODES) ? (g_deg[v] - 1) : 0;
    s[t] = c;
    __syncthreads();
    for (int o = 1; o < 512; o <<= 1) {
        int val = (t >= o) ? s[t - o] : 0;
        __syncthreads();
        s[t] += val;
        __syncthreads();
    }
    if (v < N_NODES) g_off[v] = s[t] - c;       // partial exclusive
    if (t == 511) g_bsum[blockIdx.x] = s[511];  // block total
}

__global__ void k_scan2(int nb) {  // nb <= 256
    __shared__ int s[256];
    int t = threadIdx.x;
    int c = (t < nb) ? g_bsum[t] : 0;
    s[t] = c;
    __syncthreads();
    for (int o = 1; o < 256; o <<= 1) {
        int val = (t >= o) ? s[t - o] : 0;
        __syncthreads();
        s[t] += val;
        __syncthreads();
    }
    if (t < nb) g_bsum[t] = s[t] - c;  // exclusive
}

__global__ void k_scan3() {
    int v = blockIdx.x * blockDim.x + threadIdx.x;
    if (v < N_NODES) {
        int o = g_off[v] + g_bsum[v >> 9];
        g_off[v] = o;
        g_cur[v] = o;
    }
    if (v == 0) g_off[N_NODES] = N_EDGES;
}

__global__ void k_scatter(const void* __restrict__ ei) {
    int e = blockIdx.x * blockDim.x + threadIdx.x;
    if (e < N_EDGES) {
        int d = load_edge(ei, 1, e);
        int s = load_edge(ei, 0, e);
        int pos = atomicAdd(&g_cur[d], 1);
        g_srcs[pos] = s;
    }
}

// ---------------- GEMM1: h1 = x @ W1  (100000x512 @ 512x64) ----------------
#define BM   64
#define BK   16
#define ASTR 68  // padded stride, multiple of 4

__global__ __launch_bounds__(256) void k_gemm1(const float* __restrict__ x,
                                               const float* __restrict__ W1) {
    __shared__ float As[BK * ASTR];  // As[k][m]
    __shared__ float Bs[BK * 64];    // Bs[k][n]
    int tid = threadIdx.x;
    int r0 = blockIdx.x * BM;
    int tm = tid >> 4, tn = tid & 15;        // 16x16 thread grid, 4x4 tile each
    int aRow = tid >> 2, aK = (tid & 3) * 4; // A loader: 64 rows x 16 k
    int bK = tid >> 4, bN = (tid & 15) * 4;  // B loader: 16 k x 64 n

    float acc[16];
#pragma unroll
    for (int i = 0; i < 16; i++) acc[i] = 0.f;

    bool aValid = (r0 + aRow) < N_NODES;
    const float* xp = x + (size_t)(r0 + aRow) * IN_DIM + aK;

    for (int kt = 0; kt < IN_DIM; kt += BK) {
        float4 av = aValid ? *(const float4*)(xp + kt) : make_float4(0.f, 0.f, 0.f, 0.f);
        float4 bv = *(const float4*)(W1 + (size_t)(kt + bK) * 64 + bN);
        __syncthreads();
        As[(aK + 0) * ASTR + aRow] = av.x;
        As[(aK + 1) * ASTR + aRow] = av.y;
        As[(aK + 2) * ASTR + aRow] = av.z;
        As[(aK + 3) * ASTR + aRow] = av.w;
        *(float4*)&Bs[bK * 64 + bN] = bv;
        __syncthreads();
#pragma unroll
        for (int kk = 0; kk < BK; kk++) {
            float4 a = *(const float4*)&As[kk * ASTR + tm * 4];
            float4 b = *(const float4*)&Bs[kk * 64 + tn * 4];
            acc[0]  = fmaf(a.x, b.x, acc[0]);
            acc[1]  = fmaf(a.x, b.y, acc[1]);
            acc[2]  = fmaf(a.x, b.z, acc[2]);
            acc[3]  = fmaf(a.x, b.w, acc[3]);
            acc[4]  = fmaf(a.y, b.x, acc[4]);
            acc[5]  = fmaf(a.y, b.y, acc[5]);
            acc[6]  = fmaf(a.y, b.z, acc[6]);
            acc[7]  = fmaf(a.y, b.w, acc[7]);
            acc[8]  = fmaf(a.z, b.x, acc[8]);
            acc[9]  = fmaf(a.z, b.y, acc[9]);
            acc[10] = fmaf(a.z, b.z, acc[10]);
            acc[11] = fmaf(a.z, b.w, acc[11]);
            acc[12] = fmaf(a.w, b.x, acc[12]);
            acc[13] = fmaf(a.w, b.y, acc[13]);
            acc[14] = fmaf(a.w, b.z, acc[14]);
            acc[15] = fmaf(a.w, b.w, acc[15]);
        }
    }
#pragma unroll
    for (int i = 0; i < 4; i++) {
        int r = r0 + tm * 4 + i;
        if (r < N_NODES) {
            float4 o = make_float4(acc[i * 4 + 0], acc[i * 4 + 1], acc[i * 4 + 2], acc[i * 4 + 3]);
            *(float4*)&g_h1[(size_t)r * HID + tn * 4] = o;
        }
    }
}

// ---------------- agg1: out1 = A_norm @ h1 + b1, relu, then h2 = out1 @ W2 ----------------
__global__ __launch_bounds__(256) void k_agg1(const float* __restrict__ b1,
                                              const float* __restrict__ W2) {
    __shared__ float W2s[HID * OUTD];  // 64x32
    __shared__ float ha[8][HID];
    int tid = threadIdx.x;
    for (int i = tid; i < HID * OUTD; i += 256) W2s[i] = W2[i];
    __syncthreads();

    int w = tid >> 5, lane = tid & 31;
    int v = blockIdx.x * 8 + w;
    if (v >= N_NODES) return;

    float dv = g_dinv[v];
    int e = g_off[v], end = g_off[v + 1];
    float a0 = 0.f, a1 = 0.f;
    for (; e < end; ++e) {
        int s = g_srcs[e];
        float wgt = dv * g_dinv[s];
        const float* hp = g_h1 + (size_t)s * HID;
        a0 = fmaf(wgt, hp[lane], a0);
        a1 = fmaf(wgt, hp[lane + 32], a1);
    }
    {   // self loop
        float wgt = dv * dv;
        const float* hp = g_h1 + (size_t)v * HID;
        a0 = fmaf(wgt, hp[lane], a0);
        a1 = fmaf(wgt, hp[lane + 32], a1);
    }
    a0 = fmaxf(a0 + b1[lane], 0.f);
    a1 = fmaxf(a1 + b1[lane + 32], 0.f);
    ha[w][lane] = a0;
    ha[w][lane + 32] = a1;
    __syncwarp();

    float acc = 0.f;
#pragma unroll
    for (int k = 0; k < HID; k++) acc = fmaf(ha[w][k], W2s[k * OUTD + lane], acc);
    g_h2[(size_t)v * OUTD + lane] = acc;
}

// ---------------- agg2: out = A_norm @ h2 + b2, log_softmax ----------------
__global__ __launch_bounds__(256) void k_agg2(const float* __restrict__ b2,
                                              float* __restrict__ out) {
    int tid = threadIdx.x;
    int w = tid >> 5, lane = tid & 31;
    int v = blockIdx.x * 8 + w;
    if (v >= N_NODES) return;

    float dv = g_dinv[v];
    int e = g_off[v], end = g_off[v + 1];
    float a = 0.f;
    for (; e < end; ++e) {
        int s = g_srcs[e];
        float wgt = dv * g_dinv[s];
        a = fmaf(wgt, g_h2[(size_t)s * OUTD + lane], a);
    }
    a = fmaf(dv * dv, g_h2[(size_t)v * OUTD + lane], a);
    a += b2[lane];

    float m = a;
#pragma unroll
    for (int o = 16; o > 0; o >>= 1) m = fmaxf(m, __shfl_xor_sync(0xffffffffu, m, o));
    float ex = expf(a - m);
    float ssum = ex;
#pragma unroll
    for (int o = 16; o > 0; o >>= 1) ssum += __shfl_xor_sync(0xffffffffu, ssum, o);
    out[(size_t)v * OUTD + lane] = a - m - logf(ssum);
}

// ---------------- launch ----------------
extern "C" void kernel_launch(void* const* d_in, const int* in_sizes, int n_in,
                              void* d_out, int out_size) {
    const float* x  = (const float*)d_in[0];
    const void*  ei = d_in[1];
    const float* W1 = (const float*)d_in[2];
    const float* b1 = (const float*)d_in[3];
    const float* W2 = (const float*)d_in[4];
    const float* b2 = (const float*)d_in[5];
    float* out = (float*)d_out;

    k_detect<<<1, 256>>>((const long long*)ei);
    k_init<<<(N_NODES + 255) / 256, 256>>>();
    k_hist<<<(N_EDGES + 255) / 256, 256>>>(ei);
    k_dinv<<<(N_NODES + 255) / 256, 256>>>();
    int nb = (N_NODES + 511) / 512;
    k_scan1<<<nb, 512>>>();
    k_scan2<<<1, 256>>>(nb);
    k_scan3<<<(N_NODES + 255) / 256, 256>>>();
    k_scatter<<<(N_EDGES + 255) / 256, 256>>>(ei);
    k_gemm1<<<(N_NODES + BM - 1) / BM, 256>>>(x, W1);
    k_agg1<<<(N_NODES + 7) / 8, 256>>>(b1, W2);
    k_agg2<<<(N_NODES + 7) / 8, 256>>>(b2, out);
}

// round 2
// speedup vs baseline: 1.1215x; 1.1215x over previous
#include <cuda_runtime.h>
#include <cuda_bf16.h>
#include <math.h>

#define N_NODES 100000
#define N_EDGES 1600000
#define IN_DIM  512
#define HID     64
#define OUTD    32

// ---------------- scratch (static device globals; no allocation) ----------------
__device__ int   g_deg[N_NODES];
__device__ float g_dinv[N_NODES];
__device__ int   g_off[N_NODES + 1];
__device__ int   g_cur[N_NODES];
__device__ int   g_srcs[N_EDGES];
__device__ float g_h1[(size_t)N_NODES * HID];   // 25.6 MB
__device__ float g_h2[(size_t)N_NODES * OUTD];  // 12.8 MB
__device__ int   g_bsum[256];
__device__ int   g_is64;

// ---------------- edge-index dtype detection (int64 vs int32) ----------------
__global__ void k_detect(const long long* __restrict__ ei) {
    __shared__ int ok;
    if (threadIdx.x == 0) ok = 1;
    __syncthreads();
    for (int j = threadIdx.x; j < 2048; j += blockDim.x) {
        long long v = ei[j];
        if (v < 0 || v >= N_NODES) atomicExch(&ok, 0);
    }
    __syncthreads();
    if (threadIdx.x == 0) g_is64 = ok;
}

__device__ __forceinline__ int load_edge(const void* ei, int part, int e) {
    if (g_is64) return (int)((const long long*)ei)[(size_t)part * N_EDGES + e];
    return ((const int*)ei)[(size_t)part * N_EDGES + e];
}

// ---------------- degree / normalization ----------------
__global__ void k_init() {
    int v = blockIdx.x * blockDim.x + threadIdx.x;
    if (v < N_NODES) g_deg[v] = 1;  // self-loop
}

__global__ void k_hist(const void* __restrict__ ei) {
    int e = blockIdx.x * blockDim.x + threadIdx.x;
    if (e < N_EDGES) atomicAdd(&g_deg[load_edge(ei, 1, e)], 1);
}

__global__ void k_dinv() {
    int v = blockIdx.x * blockDim.x + threadIdx.x;
    if (v < N_NODES) g_dinv[v] = rsqrtf((float)g_deg[v]);
}

// ---------------- exclusive scan of (deg-1) to build CSR offsets ----------------
__global__ void k_scan1() {
    __shared__ int s[512];
    int t = threadIdx.x;
    int v = blockIdx.x * 512 + t;
    int c = (v < N_NODES) ? (g_deg[v] - 1) : 0;
    s[t] = c;
    __syncthreads();
    for (int o = 1; o < 512; o <<= 1) {
        int val = (t >= o) ? s[t - o] : 0;
        __syncthreads();
        s[t] += val;
        __syncthreads();
    }
    if (v < N_NODES) g_off[v] = s[t] - c;
    if (t == 511) g_bsum[blockIdx.x] = s[511];
}

__global__ void k_scan2(int nb) {
    __shared__ int s[256];
    int t = threadIdx.x;
    int c = (t < nb) ? g_bsum[t] : 0;
    s[t] = c;
    __syncthreads();
    for (int o = 1; o < 256; o <<= 1) {
        int val = (t >= o) ? s[t - o] : 0;
        __syncthreads();
        s[t] += val;
        __syncthreads();
    }
    if (t < nb) g_bsum[t] = s[t] - c;
}

__global__ void k_scan3() {
    int v = blockIdx.x * blockDim.x + threadIdx.x;
    if (v < N_NODES) {
        int o = g_off[v] + g_bsum[v >> 9];
        g_off[v] = o;
        g_cur[v] = o;
    }
    if (v == 0) g_off[N_NODES] = N_EDGES;
}

__global__ void k_scatter(const void* __restrict__ ei) {
    int e = blockIdx.x * blockDim.x + threadIdx.x;
    if (e < N_EDGES) {
        int d = load_edge(ei, 1, e);
        int s = load_edge(ei, 0, e);
        int pos = atomicAdd(&g_cur[d], 1);
        g_srcs[pos] = s;
    }
}

// ---------------- GEMM1 via bf16 tensor cores with hi/lo split ----------------
// h1 = x @ W1, 100000x512 @ 512x64. Error-compensated: x = xh + xl, W = wh + wl
// (bf16 each); accumulate xh*wh + xh*wl + xl*wh in f32 -> ~4e-6 rel error.
#define BM 128
#define BK 32
#define ASTR 40   // bf16 stride per row (20 32-bit words) -> conflict-free

__device__ __forceinline__ void mma16816(float* c, const unsigned* a, const unsigned* b) {
    asm volatile(
        "mma.sync.aligned.m16n8k16.row.col.f32.bf16.bf16.f32 "
        "{%0,%1,%2,%3}, {%4,%5,%6,%7}, {%8,%9}, {%0,%1,%2,%3};\n"
        : "+f"(c[0]), "+f"(c[1]), "+f"(c[2]), "+f"(c[3])
        : "r"(a[0]), "r"(a[1]), "r"(a[2]), "r"(a[3]), "r"(b[0]), "r"(b[1]));
}

__global__ __launch_bounds__(256) void k_gemm1(const float* __restrict__ x,
                                               const float* __restrict__ W1) {
    __shared__ __nv_bfloat16 As_h[BM * ASTR];
    __shared__ __nv_bfloat16 As_l[BM * ASTR];
    __shared__ __nv_bfloat16 Bs_h[64 * ASTR];
    __shared__ __nv_bfloat16 Bs_l[64 * ASTR];

    const int t = threadIdx.x;
    const int warp = t >> 5, lane = t & 31;
    const int q = lane & 3, lr = lane >> 2;
    const int r0 = blockIdx.x * BM;

    float acc[8][4];
#pragma unroll
    for (int i = 0; i < 8; i++)
#pragma unroll
        for (int j = 0; j < 4; j++) acc[i][j] = 0.f;

    for (int kt = 0; kt < IN_DIM; kt += BK) {
        // ---- load & split A tile: 128 rows x 32 cols f32 -> hi/lo bf16
#pragma unroll
        for (int i = 0; i < 4; i++) {
            int f4 = t + 256 * i;           // 0..1023
            int row = f4 >> 3, c4 = f4 & 7; // col block of 4 floats
            int gr = r0 + row;
            float4 v = (gr < N_NODES)
                           ? *(const float4*)(x + (size_t)gr * IN_DIM + kt + c4 * 4)
                           : make_float4(0.f, 0.f, 0.f, 0.f);
            __nv_bfloat16 h0 = __float2bfloat16(v.x);
            __nv_bfloat16 h1 = __float2bfloat16(v.y);
            __nv_bfloat16 h2 = __float2bfloat16(v.z);
            __nv_bfloat16 h3 = __float2bfloat16(v.w);
            __nv_bfloat16 l0 = __float2bfloat16(v.x - __bfloat162float(h0));
            __nv_bfloat16 l1 = __float2bfloat16(v.y - __bfloat162float(h1));
            __nv_bfloat16 l2 = __float2bfloat16(v.z - __bfloat162float(h2));
            __nv_bfloat16 l3 = __float2bfloat16(v.w - __bfloat162float(h3));
            __nv_bfloat162* ph = (__nv_bfloat162*)As_h;
            __nv_bfloat162* pl = (__nv_bfloat162*)As_l;
            int wi = row * (ASTR / 2) + c4 * 2;
            ph[wi]     = __nv_bfloat162{h0, h1};
            ph[wi + 1] = __nv_bfloat162{h2, h3};
            pl[wi]     = __nv_bfloat162{l0, l1};
            pl[wi + 1] = __nv_bfloat162{l2, l3};
        }
        // ---- load & split B tile transposed: Bs[n][k] = W1[kt+k][n]
#pragma unroll
        for (int i = 0; i < 2; i++) {
            int f4 = t + 256 * i;            // 0..511
            int k = f4 >> 4, c4 = f4 & 15;
            float4 v = *(const float4*)(W1 + (size_t)(kt + k) * 64 + c4 * 4);
            float vv[4] = {v.x, v.y, v.z, v.w};
#pragma unroll
            for (int j = 0; j < 4; j++) {
                int n = c4 * 4 + j;
                __nv_bfloat16 h = __float2bfloat16(vv[j]);
                Bs_h[n * ASTR + k] = h;
                Bs_l[n * ASTR + k] = __float2bfloat16(vv[j] - __bfloat162float(h));
            }
        }
        __syncthreads();

        const unsigned* Ah = (const unsigned*)As_h;
        const unsigned* Al = (const unsigned*)As_l;
        const unsigned* Bh = (const unsigned*)Bs_h;
        const unsigned* Bl = (const unsigned*)Bs_l;
        const int S = ASTR / 2;  // 20 words per row

#pragma unroll
        for (int ks = 0; ks < 2; ks++) {
            int kb = q + ks * 8;
            int ra = warp * 16 + lr;
            unsigned ah[4], al[4];
            ah[0] = Ah[ra * S + kb];
            ah[1] = Ah[(ra + 8) * S + kb];
            ah[2] = Ah[ra * S + kb + 4];
            ah[3] = Ah[(ra + 8) * S + kb + 4];
            al[0] = Al[ra * S + kb];
            al[1] = Al[(ra + 8) * S + kb];
            al[2] = Al[ra * S + kb + 4];
            al[3] = Al[(ra + 8) * S + kb + 4];
#pragma unroll
            for (int nt = 0; nt < 8; nt++) {
                int nb = (nt * 8 + lr) * S + kb;
                unsigned bh[2], bl[2];
                bh[0] = Bh[nb];
                bh[1] = Bh[nb + 4];
                bl[0] = Bl[nb];
                bl[1] = Bl[nb + 4];
                mma16816(acc[nt], ah, bh);
                mma16816(acc[nt], ah, bl);
                mma16816(acc[nt], al, bh);
            }
        }
        __syncthreads();
    }

    // ---- epilogue: write h1
    int rb = r0 + warp * 16 + lr;
#pragma unroll
    for (int nt = 0; nt < 8; nt++) {
        int col = nt * 8 + q * 2;
        if (rb < N_NODES)
            *(float2*)&g_h1[(size_t)rb * HID + col] = make_float2(acc[nt][0], acc[nt][1]);
        if (rb + 8 < N_NODES)
            *(float2*)&g_h1[(size_t)(rb + 8) * HID + col] = make_float2(acc[nt][2], acc[nt][3]);
    }
}

// ---------------- agg1: out1 = A_norm @ h1 + b1, relu, then h2 = out1 @ W2 ----------------
__global__ __launch_bounds__(256) void k_agg1(const float* __restrict__ b1,
                                              const float* __restrict__ W2) {
    __shared__ float W2s[HID * OUTD];
    __shared__ float ha[8][HID];
    int tid = threadIdx.x;
    for (int i = tid; i < HID * OUTD; i += 256) W2s[i] = W2[i];
    __syncthreads();

    int w = tid >> 5, lane = tid & 31;
    int v = blockIdx.x * 8 + w;
    if (v >= N_NODES) return;

    float dv = g_dinv[v];
    int e = g_off[v], end = g_off[v + 1];
    float a0 = 0.f, a1 = 0.f;
    for (; e < end; ++e) {
        int s = g_srcs[e];
        float wgt = dv * g_dinv[s];
        const float* hp = g_h1 + (size_t)s * HID;
        a0 = fmaf(wgt, hp[lane], a0);
        a1 = fmaf(wgt, hp[lane + 32], a1);
    }
    {
        float wgt = dv * dv;
        const float* hp = g_h1 + (size_t)v * HID;
        a0 = fmaf(wgt, hp[lane], a0);
        a1 = fmaf(wgt, hp[lane + 32], a1);
    }
    a0 = fmaxf(a0 + b1[lane], 0.f);
    a1 = fmaxf(a1 + b1[lane + 32], 0.f);
    ha[w][lane] = a0;
    ha[w][lane + 32] = a1;
    __syncwarp();

    float acc = 0.f;
#pragma unroll
    for (int k = 0; k < HID; k++) acc = fmaf(ha[w][k], W2s[k * OUTD + lane], acc);
    g_h2[(size_t)v * OUTD + lane] = acc;
}

// ---------------- agg2: out = A_norm @ h2 + b2, log_softmax ----------------
__global__ __launch_bounds__(256) void k_agg2(const float* __restrict__ b2,
                                              float* __restrict__ out) {
    int tid = threadIdx.x;
    int w = tid >> 5, lane = tid & 31;
    int v = blockIdx.x * 8 + w;
    if (v >= N_NODES) return;

    float dv = g_dinv[v];
    int e = g_off[v], end = g_off[v + 1];
    float a = 0.f;
    for (; e < end; ++e) {
        int s = g_srcs[e];
        float wgt = dv * g_dinv[s];
        a = fmaf(wgt, g_h2[(size_t)s * OUTD + lane], a);
    }
    a = fmaf(dv * dv, g_h2[(size_t)v * OUTD + lane], a);
    a += b2[lane];

    float m = a;
#pragma unroll
    for (int o = 16; o > 0; o >>= 1) m = fmaxf(m, __shfl_xor_sync(0xffffffffu, m, o));
    float ex = expf(a - m);
    float ssum = ex;
#pragma unroll
    for (int o = 16; o > 0; o >>= 1) ssum += __shfl_xor_sync(0xffffffffu, ssum, o);
    out[(size_t)v * OUTD + lane] = a - m - logf(ssum);
}

// ---------------- launch ----------------
extern "C" void kernel_launch(void* const* d_in, const int* in_sizes, int n_in,
                              void* d_out, int out_size) {
    const float* x  = (const float*)d_in[0];
    const void*  ei = d_in[1];
    const float* W1 = (const float*)d_in[2];
    const float* b1 = (const float*)d_in[3];
    const float* W2 = (const float*)d_in[4];
    const float* b2 = (const float*)d_in[5];
    float* out = (float*)d_out;

    k_detect<<<1, 256>>>((const long long*)ei);
    k_init<<<(N_NODES + 255) / 256, 256>>>();
    k_hist<<<(N_EDGES + 255) / 256, 256>>>(ei);
    k_dinv<<<(N_NODES + 255) / 256, 256>>>();
    int nb = (N_NODES + 511) / 512;
    k_scan1<<<nb, 512>>>();
    k_scan2<<<1, 256>>>(nb);
    k_scan3<<<(N_NODES + 255) / 256, 256>>>();
    k_scatter<<<(N_EDGES + 255) / 256, 256>>>(ei);
    k_gemm1<<<(N_NODES + BM - 1) / BM, 256>>>(x, W1);
    k_agg1<<<(N_NODES + 7) / 8, 256>>>(b1, W2);
    k_agg2<<<(N_NODES + 7) / 8, 256>>>(b2, out);
}

// round 3
// speedup vs baseline: 1.1656x; 1.0392x over previous
#include <cuda_runtime.h>
#include <cuda_bf16.h>
#include <math.h>

#define N_NODES 100000
#define N_EDGES 1600000
#define IN_DIM  512
#define HID     64
#define OUTD    32

// ---------------- scratch (static device globals; no allocation) ----------------
__device__ int   g_deg[N_NODES];
__device__ float g_dinv[N_NODES];
__device__ int   g_off[N_NODES + 1];
__device__ int   g_cur[N_NODES];
__device__ int   g_srcs[N_EDGES];
__device__ float g_wgt[N_EDGES];
__device__ float g_h1[(size_t)N_NODES * HID];   // 25.6 MB
__device__ float g_h2[(size_t)N_NODES * OUTD];  // 12.8 MB
__device__ int   g_bsum[256];
__device__ int   g_is64;

// ---------------- edge-index dtype detection (int64 vs int32) ----------------
__global__ void k_detect(const long long* __restrict__ ei) {
    __shared__ int ok;
    if (threadIdx.x == 0) ok = 1;
    __syncthreads();
    for (int j = threadIdx.x; j < 2048; j += blockDim.x) {
        long long v = ei[j];
        if (v < 0 || v >= N_NODES) atomicExch(&ok, 0);
    }
    __syncthreads();
    if (threadIdx.x == 0) g_is64 = ok;
}

__device__ __forceinline__ int load_edge(const void* ei, int part, int e) {
    if (g_is64) return (int)((const long long*)ei)[(size_t)part * N_EDGES + e];
    return ((const int*)ei)[(size_t)part * N_EDGES + e];
}

// ---------------- degree / hist ----------------
__global__ void k_init() {
    int v = blockIdx.x * blockDim.x + threadIdx.x;
    if (v < N_NODES) g_deg[v] = 1;  // self-loop
}

__global__ void k_hist(const void* __restrict__ ei) {
    int e = blockIdx.x * blockDim.x + threadIdx.x;
    if (e < N_EDGES) atomicAdd(&g_deg[load_edge(ei, 1, e)], 1);
}

// ---------------- exclusive scan of (deg-1) to build CSR offsets ----------------
__global__ void k_scan1() {
    __shared__ int s[512];
    int t = threadIdx.x;
    int v = blockIdx.x * 512 + t;
    int c = (v < N_NODES) ? (g_deg[v] - 1) : 0;
    s[t] = c;
    __syncthreads();
    for (int o = 1; o < 512; o <<= 1) {
        int val = (t >= o) ? s[t - o] : 0;
        __syncthreads();
        s[t] += val;
        __syncthreads();
    }
    if (v < N_NODES) g_off[v] = s[t] - c;
    if (t == 511) g_bsum[blockIdx.x] = s[511];
}

__global__ void k_scan2(int nb) {
    __shared__ int s[256];
    int t = threadIdx.x;
    int c = (t < nb) ? g_bsum[t] : 0;
    s[t] = c;
    __syncthreads();
    for (int o = 1; o < 256; o <<= 1) {
        int val = (t >= o) ? s[t - o] : 0;
        __syncthreads();
        s[t] += val;
        __syncthreads();
    }
    if (t < nb) g_bsum[t] = s[t] - c;
}

__global__ void k_scan3() {  // finalize offsets + compute dinv
    int v = blockIdx.x * blockDim.x + threadIdx.x;
    if (v < N_NODES) {
        int o = g_off[v] + g_bsum[v >> 9];
        g_off[v] = o;
        g_cur[v] = o;
        g_dinv[v] = rsqrtf((float)g_deg[v]);
    }
    if (v == 0) g_off[N_NODES] = N_EDGES;
}

__global__ void k_scatter(const void* __restrict__ ei) {
    int e = blockIdx.x * blockDim.x + threadIdx.x;
    if (e < N_EDGES) {
        int d = load_edge(ei, 1, e);
        int s = load_edge(ei, 0, e);
        int pos = atomicAdd(&g_cur[d], 1);
        g_srcs[pos] = s;
        g_wgt[pos] = g_dinv[s] * g_dinv[d];
    }
}

// ---------------- GEMM1 via bf16 tensor cores with hi/lo split ----------------
#define BM 128
#define BK 32
#define ASTR 40   // bf16 stride per row (20 32-bit words) -> conflict-free

__device__ __forceinline__ void mma16816(float* c, const unsigned* a, const unsigned* b) {
    asm volatile(
        "mma.sync.aligned.m16n8k16.row.col.f32.bf16.bf16.f32 "
        "{%0,%1,%2,%3}, {%4,%5,%6,%7}, {%8,%9}, {%0,%1,%2,%3};\n"
        : "+f"(c[0]), "+f"(c[1]), "+f"(c[2]), "+f"(c[3])
        : "r"(a[0]), "r"(a[1]), "r"(a[2]), "r"(a[3]), "r"(b[0]), "r"(b[1]));
}

__global__ __launch_bounds__(256) void k_gemm1(const float* __restrict__ x,
                                               const float* __restrict__ W1) {
    __shared__ __nv_bfloat16 As_h[BM * ASTR];
    __shared__ __nv_bfloat16 As_l[BM * ASTR];
    __shared__ __nv_bfloat16 Bs_h[64 * ASTR];
    __shared__ __nv_bfloat16 Bs_l[64 * ASTR];

    const int t = threadIdx.x;
    const int warp = t >> 5, lane = t & 31;
    const int q = lane & 3, lr = lane >> 2;
    const int r0 = blockIdx.x * BM;

    float acc[8][4];
#pragma unroll
    for (int i = 0; i < 8; i++)
#pragma unroll
        for (int j = 0; j < 4; j++) acc[i][j] = 0.f;

    for (int kt = 0; kt < IN_DIM; kt += BK) {
        // ---- load & split A tile: 128 rows x 32 cols f32 -> hi/lo bf16
#pragma unroll
        for (int i = 0; i < 4; i++) {
            int f4 = t + 256 * i;
            int row = f4 >> 3, c4 = f4 & 7;
            int gr = r0 + row;
            float4 v = (gr < N_NODES)
                           ? __ldcs((const float4*)(x + (size_t)gr * IN_DIM + kt + c4 * 4))
                           : make_float4(0.f, 0.f, 0.f, 0.f);
            __nv_bfloat16 h0 = __float2bfloat16(v.x);
            __nv_bfloat16 h1 = __float2bfloat16(v.y);
            __nv_bfloat16 h2 = __float2bfloat16(v.z);
            __nv_bfloat16 h3 = __float2bfloat16(v.w);
            __nv_bfloat16 l0 = __float2bfloat16(v.x - __bfloat162float(h0));
            __nv_bfloat16 l1 = __float2bfloat16(v.y - __bfloat162float(h1));
            __nv_bfloat16 l2 = __float2bfloat16(v.z - __bfloat162float(h2));
            __nv_bfloat16 l3 = __float2bfloat16(v.w - __bfloat162float(h3));
            __nv_bfloat162* ph = (__nv_bfloat162*)As_h;
            __nv_bfloat162* pl = (__nv_bfloat162*)As_l;
            int wi = row * (ASTR / 2) + c4 * 2;
            ph[wi]     = __nv_bfloat162{h0, h1};
            ph[wi + 1] = __nv_bfloat162{h2, h3};
            pl[wi]     = __nv_bfloat162{l0, l1};
            pl[wi + 1] = __nv_bfloat162{l2, l3};
        }
        // ---- load & split B tile transposed: Bs[n][k] = W1[kt+k][n]
#pragma unroll
        for (int i = 0; i < 2; i++) {
            int f4 = t + 256 * i;
            int k = f4 >> 4, c4 = f4 & 15;
            float4 v = *(const float4*)(W1 + (size_t)(kt + k) * 64 + c4 * 4);
            float vv[4] = {v.x, v.y, v.z, v.w};
#pragma unroll
            for (int j = 0; j < 4; j++) {
                int n = c4 * 4 + j;
                __nv_bfloat16 h = __float2bfloat16(vv[j]);
                Bs_h[n * ASTR + k] = h;
                Bs_l[n * ASTR + k] = __float2bfloat16(vv[j] - __bfloat162float(h));
            }
        }
        __syncthreads();

        const unsigned* Ah = (const unsigned*)As_h;
        const unsigned* Al = (const unsigned*)As_l;
        const unsigned* Bh = (const unsigned*)Bs_h;
        const unsigned* Bl = (const unsigned*)Bs_l;
        const int S = ASTR / 2;

#pragma unroll
        for (int ks = 0; ks < 2; ks++) {
            int kb = q + ks * 8;
            int ra = warp * 16 + lr;
            unsigned ah[4], al[4];
            ah[0] = Ah[ra * S + kb];
            ah[1] = Ah[(ra + 8) * S + kb];
            ah[2] = Ah[ra * S + kb + 4];
            ah[3] = Ah[(ra + 8) * S + kb + 4];
            al[0] = Al[ra * S + kb];
            al[1] = Al[(ra + 8) * S + kb];
            al[2] = Al[ra * S + kb + 4];
            al[3] = Al[(ra + 8) * S + kb + 4];
#pragma unroll
            for (int nt = 0; nt < 8; nt++) {
                int nb = (nt * 8 + lr) * S + kb;
                unsigned bh[2], bl[2];
                bh[0] = Bh[nb];
                bh[1] = Bh[nb + 4];
                bl[0] = Bl[nb];
                bl[1] = Bl[nb + 4];
                mma16816(acc[nt], ah, bh);
                mma16816(acc[nt], ah, bl);
                mma16816(acc[nt], al, bh);
            }
        }
        __syncthreads();
    }

    int rb = r0 + warp * 16 + lr;
#pragma unroll
    for (int nt = 0; nt < 8; nt++) {
        int col = nt * 8 + q * 2;
        if (rb < N_NODES)
            *(float2*)&g_h1[(size_t)rb * HID + col] = make_float2(acc[nt][0], acc[nt][1]);
        if (rb + 8 < N_NODES)
            *(float2*)&g_h1[(size_t)(rb + 8) * HID + col] = make_float2(acc[nt][2], acc[nt][3]);
    }
}

// ---------------- agg1: out1 = A_norm @ h1 + b1, relu, then h2 = out1 @ W2 ----------------
__global__ __launch_bounds__(256) void k_agg1(const float* __restrict__ b1,
                                              const float* __restrict__ W2) {
    __shared__ float W2s[HID * OUTD];
    __shared__ float ha[8][HID];
    int tid = threadIdx.x;
    for (int i = tid; i < HID * OUTD; i += 256) W2s[i] = W2[i];
    __syncthreads();

    int w = tid >> 5, lane = tid & 31;
    int v = blockIdx.x * 8 + w;
    if (v >= N_NODES) return;

    const float2* __restrict__ H = (const float2*)g_h1;  // row stride 32 float2
    float dv = g_dinv[v];
    float ax = 0.f, ay = 0.f;

    {   // self loop
        float2 p = H[(size_t)v * 32 + lane];
        float wgt = dv * dv;
        ax = fmaf(wgt, p.x, ax);
        ay = fmaf(wgt, p.y, ay);
    }
    int e = g_off[v], end = g_off[v + 1];
    for (; e + 4 <= end; e += 4) {
        int s0 = g_srcs[e], s1 = g_srcs[e + 1], s2 = g_srcs[e + 2], s3 = g_srcs[e + 3];
        float w0 = g_wgt[e], w1 = g_wgt[e + 1], w2 = g_wgt[e + 2], w3 = g_wgt[e + 3];
        float2 p0 = H[(size_t)s0 * 32 + lane];
        float2 p1 = H[(size_t)s1 * 32 + lane];
        float2 p2 = H[(size_t)s2 * 32 + lane];
        float2 p3 = H[(size_t)s3 * 32 + lane];
        ax = fmaf(w0, p0.x, ax); ay = fmaf(w0, p0.y, ay);
        ax = fmaf(w1, p1.x, ax); ay = fmaf(w1, p1.y, ay);
        ax = fmaf(w2, p2.x, ax); ay = fmaf(w2, p2.y, ay);
        ax = fmaf(w3, p3.x, ax); ay = fmaf(w3, p3.y, ay);
    }
    for (; e < end; ++e) {
        int s = g_srcs[e];
        float wg = g_wgt[e];
        float2 p = H[(size_t)s * 32 + lane];
        ax = fmaf(wg, p.x, ax);
        ay = fmaf(wg, p.y, ay);
    }
    ax = fmaxf(ax + b1[2 * lane], 0.f);
    ay = fmaxf(ay + b1[2 * lane + 1], 0.f);
    ha[w][2 * lane]     = ax;
    ha[w][2 * lane + 1] = ay;
    __syncwarp();

    float acc = 0.f;
#pragma unroll
    for (int k = 0; k < HID; k++) acc = fmaf(ha[w][k], W2s[k * OUTD + lane], acc);
    g_h2[(size_t)v * OUTD + lane] = acc;
}

// ---------------- agg2: out = A_norm @ h2 + b2, log_softmax ----------------
__global__ __launch_bounds__(256) void k_agg2(const float* __restrict__ b2,
                                              float* __restrict__ out) {
    int tid = threadIdx.x;
    int w = tid >> 5, lane = tid & 31;
    int v = blockIdx.x * 8 + w;
    if (v >= N_NODES) return;

    const float* __restrict__ H = g_h2;
    float dv = g_dinv[v];
    float a = dv * dv * H[(size_t)v * OUTD + lane];

    int e = g_off[v], end = g_off[v + 1];
    for (; e + 4 <= end; e += 4) {
        int s0 = g_srcs[e], s1 = g_srcs[e + 1], s2 = g_srcs[e + 2], s3 = g_srcs[e + 3];
        float w0 = g_wgt[e], w1 = g_wgt[e + 1], w2 = g_wgt[e + 2], w3 = g_wgt[e + 3];
        float p0 = H[(size_t)s0 * OUTD + lane];
        float p1 = H[(size_t)s1 * OUTD + lane];
        float p2 = H[(size_t)s2 * OUTD + lane];
        float p3 = H[(size_t)s3 * OUTD + lane];
        a = fmaf(w0, p0, a);
        a = fmaf(w1, p1, a);
        a = fmaf(w2, p2, a);
        a = fmaf(w3, p3, a);
    }
    for (; e < end; ++e) a = fmaf(g_wgt[e], H[(size_t)g_srcs[e] * OUTD + lane], a);
    a += b2[lane];

    float m = a;
#pragma unroll
    for (int o = 16; o > 0; o >>= 1) m = fmaxf(m, __shfl_xor_sync(0xffffffffu, m, o));
    float ex = expf(a - m);
    float ssum = ex;
#pragma unroll
    for (int o = 16; o > 0; o >>= 1) ssum += __shfl_xor_sync(0xffffffffu, ssum, o);
    out[(size_t)v * OUTD + lane] = a - m - logf(ssum);
}

// ---------------- launch ----------------
extern "C" void kernel_launch(void* const* d_in, const int* in_sizes, int n_in,
                              void* d_out, int out_size) {
    const float* x  = (const float*)d_in[0];
    const void*  ei = d_in[1];
    const float* W1 = (const float*)d_in[2];
    const float* b1 = (const float*)d_in[3];
    const float* W2 = (const float*)d_in[4];
    const float* b2 = (const float*)d_in[5];
    float* out = (float*)d_out;

    k_detect<<<1, 256>>>((const long long*)ei);
    k_init<<<(N_NODES + 255) / 256, 256>>>();
    k_hist<<<(N_EDGES + 255) / 256, 256>>>(ei);
    // gemm1 has no dependency on the edge pipeline; position 4 so the profiler
    // (which has been sampling our 4th launch) captures it next round.
    k_gemm1<<<(N_NODES + BM - 1) / BM, 256>>>(x, W1);
    int nb = (N_NODES + 511) / 512;
    k_scan1<<<nb, 512>>>();
    k_scan2<<<1, 256>>>(nb);
    k_scan3<<<(N_NODES + 255) / 256, 256>>>();
    k_scatter<<<(N_EDGES + 255) / 256, 256>>>(ei);
    k_agg1<<<(N_NODES + 7) / 8, 256>>>(b1, W2);
    k_agg2<<<(N_NODES + 7) / 8, 256>>>(b2, out);
}